// round 17
// baseline (speedup 1.0000x reference)
#include <cuda_runtime.h>
#include <math.h>

#define D 96
#define N_MAX 50000
#define E_MAX 800000
#define ND_MAX (N_MAX * 96)

// Scratch (no cudaMalloc allowed)
__device__ __align__(16) float g_pooled[ND_MAX];
__device__ __align__(16) float g_h[ND_MAX];
__device__ float g_sum[D];
__device__ float g_sumsq[D];
__device__ int g_count[N_MAX];
__device__ int g_offset[N_MAX + 1];
__device__ int g_cursor[N_MAX];
__device__ int g_edge_src[E_MAX];

// ---------------------------------------------------------------------------
// Kernel 0: zero per-dst counts + BN accumulators
// ---------------------------------------------------------------------------
__global__ void zero_kernel(int N) {
    int i = blockIdx.x * blockDim.x + threadIdx.x;
    if (i < N) g_count[i] = 0;
    if (i < D) { g_sum[i] = 0.0f; g_sumsq[i] = 0.0f; }
}

// ---------------------------------------------------------------------------
// Kernel 1: count incoming edges per destination
// ---------------------------------------------------------------------------
__global__ void count_kernel(const int* __restrict__ dst, int E) {
    int e = blockIdx.x * blockDim.x + threadIdx.x;
    if (e < E) atomicAdd(&g_count[dst[e]], 1);
}

// ---------------------------------------------------------------------------
// Kernel 2: exclusive scan of counts -> offsets (+ cursor copy).
// Single block of 1024 threads; each thread serially sums a contiguous chunk,
// block-scans the 1024 partials (warp shfl + smem), then writes its chunk.
// ---------------------------------------------------------------------------
__global__ void scan_kernel(int N) {
    __shared__ int warp_sums[32];
    int tid = threadIdx.x;
    int lane = tid & 31, wid = tid >> 5;
    int per = (N + 1023) / 1024;
    int start = tid * per;
    int end = min(start + per, N);

    int sum = 0;
    for (int i = start; i < end; i++) sum += g_count[i];

    // inclusive scan of per-thread sums
    int v = sum;
    #pragma unroll
    for (int o = 1; o < 32; o <<= 1) {
        int n = __shfl_up_sync(0xFFFFFFFFu, v, o);
        if (lane >= o) v += n;
    }
    if (lane == 31) warp_sums[wid] = v;
    __syncthreads();
    if (wid == 0) {
        int wv = warp_sums[lane];
        #pragma unroll
        for (int o = 1; o < 32; o <<= 1) {
            int n = __shfl_up_sync(0xFFFFFFFFu, wv, o);
            if (lane >= o) wv += n;
        }
        warp_sums[lane] = wv;
    }
    __syncthreads();

    int excl = v - sum + (wid > 0 ? warp_sums[wid - 1] : 0);
    int running = excl;
    for (int i = start; i < end; i++) {
        int c = g_count[i];
        g_offset[i] = running;
        g_cursor[i] = running;
        running += c;
    }
    if (tid == 1023) g_offset[N] = excl + sum;  // last thread's excl+sum = total E
}

// ---------------------------------------------------------------------------
// Kernel 3: fill edge lists (src indices grouped by dst)
// ---------------------------------------------------------------------------
__global__ void fill_kernel(const int* __restrict__ src,
                            const int* __restrict__ dst, int E) {
    int e = blockIdx.x * blockDim.x + threadIdx.x;
    if (e < E) {
        int idx = atomicAdd(&g_cursor[dst[e]], 1);
        g_edge_src[idx] = src[e];
    }
}

// ---------------------------------------------------------------------------
// Kernel 4: atomic-free gather pooling.
// One warp per node (grid-stride); lane L owns columns L, L+32, L+64.
// pooled[n] = (1+eps)*feature[n] + sum over incoming src rows.
// Writes pooled ONCE (19.2 MB) instead of 307 MB of L2 reductions.
// ---------------------------------------------------------------------------
__global__ void gather_kernel(const float* __restrict__ feature,
                              const float* __restrict__ eps, int N) {
    int gw = (blockIdx.x * blockDim.x + threadIdx.x) >> 5;
    int lane = threadIdx.x & 31;
    int num_warps = (gridDim.x * blockDim.x) >> 5;
    float scale = 1.0f + eps[0];
    int c0 = lane, c1 = lane + 32, c2 = lane + 64;

    for (int n = gw; n < N; n += num_warps) {
        const float* fn = feature + (long long)n * D;
        float a0 = scale * fn[c0];
        float a1 = scale * fn[c1];
        float a2 = scale * fn[c2];
        int beg = g_offset[n];
        int end = g_offset[n + 1];
        #pragma unroll 4
        for (int e = beg; e < end; e++) {
            int s = g_edge_src[e];                    // uniform across warp
            const float* fr = feature + (long long)s * D;
            a0 += fr[c0];                             // coalesced 128B
            a1 += fr[c1];
            a2 += fr[c2];
        }
        float* pn = g_pooled + (long long)n * D;
        pn[c0] = a0; pn[c1] = a1; pn[c2] = a2;
    }
}

// ---------------------------------------------------------------------------
// Kernel 5: fused MLP  h = relu(pooled @ W1 + b1) @ W2 + b2, with BN partial
// sums. 4-row blocking (unchanged from 139.2us version).
// ---------------------------------------------------------------------------
#define MLP_WARPS 8
#define MLP_BLOCKS 296

__global__ void mlp_kernel(const float* __restrict__ W1,
                           const float* __restrict__ b1,
                           const float* __restrict__ W2,
                           const float* __restrict__ b2, int N) {
    extern __shared__ float sm[];
    float* W1s = sm;                       // 9216 floats
    float* W2s = sm + 9216;                // 9216
    float* b1s = sm + 18432;               // 96
    float* b2s = sm + 18528;               // 96
    float4* stage = (float4*)(sm + 18624); // MLP_WARPS * 96 float4

    int tid = threadIdx.x;
    for (int i = tid; i < D * D; i += blockDim.x) {
        W1s[i] = W1[i];
        W2s[i] = W2[i];
    }
    if (tid < D) { b1s[tid] = b1[tid]; b2s[tid] = b2[tid]; }
    __syncthreads();

    int w = tid >> 5, lane = tid & 31;
    float4* st = stage + w * D;
    int c0 = lane, c1 = lane + 32, c2 = lane + 64;

    float s0 = 0.f, s1 = 0.f, s2 = 0.f;
    float q0 = 0.f, q1 = 0.f, q2 = 0.f;

    for (int r0 = (blockIdx.x * MLP_WARPS + w) * 4; r0 < N;
         r0 += gridDim.x * MLP_WARPS * 4) {
        const float* p = g_pooled + (long long)r0 * D;
        st[c0] = make_float4(p[c0], p[D + c0], p[2 * D + c0], p[3 * D + c0]);
        st[c1] = make_float4(p[c1], p[D + c1], p[2 * D + c1], p[3 * D + c1]);
        st[c2] = make_float4(p[c2], p[D + c2], p[2 * D + c2], p[3 * D + c2]);
        __syncwarp();

        float A0[4], A1[4], A2[4];
        #pragma unroll
        for (int j = 0; j < 4; j++) { A0[j] = b1s[c0]; A1[j] = b1s[c1]; A2[j] = b1s[c2]; }
        #pragma unroll 8
        for (int k = 0; k < D; k++) {
            float4 v = st[k];
            float w0 = W1s[k * D + c0];
            float w1 = W1s[k * D + c1];
            float w2 = W1s[k * D + c2];
            A0[0] = fmaf(v.x, w0, A0[0]); A0[1] = fmaf(v.y, w0, A0[1]);
            A0[2] = fmaf(v.z, w0, A0[2]); A0[3] = fmaf(v.w, w0, A0[3]);
            A1[0] = fmaf(v.x, w1, A1[0]); A1[1] = fmaf(v.y, w1, A1[1]);
            A1[2] = fmaf(v.z, w1, A1[2]); A1[3] = fmaf(v.w, w1, A1[3]);
            A2[0] = fmaf(v.x, w2, A2[0]); A2[1] = fmaf(v.y, w2, A2[1]);
            A2[2] = fmaf(v.z, w2, A2[2]); A2[3] = fmaf(v.w, w2, A2[3]);
        }
        #pragma unroll
        for (int j = 0; j < 4; j++) {
            A0[j] = fmaxf(A0[j], 0.f); A1[j] = fmaxf(A1[j], 0.f); A2[j] = fmaxf(A2[j], 0.f);
        }
        __syncwarp();
        st[c0] = make_float4(A0[0], A0[1], A0[2], A0[3]);
        st[c1] = make_float4(A1[0], A1[1], A1[2], A1[3]);
        st[c2] = make_float4(A2[0], A2[1], A2[2], A2[3]);
        __syncwarp();

        float H0[4], H1[4], H2[4];
        #pragma unroll
        for (int j = 0; j < 4; j++) { H0[j] = b2s[c0]; H1[j] = b2s[c1]; H2[j] = b2s[c2]; }
        #pragma unroll 8
        for (int k = 0; k < D; k++) {
            float4 v = st[k];
            float w0 = W2s[k * D + c0];
            float w1 = W2s[k * D + c1];
            float w2 = W2s[k * D + c2];
            H0[0] = fmaf(v.x, w0, H0[0]); H0[1] = fmaf(v.y, w0, H0[1]);
            H0[2] = fmaf(v.z, w0, H0[2]); H0[3] = fmaf(v.w, w0, H0[3]);
            H1[0] = fmaf(v.x, w1, H1[0]); H1[1] = fmaf(v.y, w1, H1[1]);
            H1[2] = fmaf(v.z, w1, H1[2]); H1[3] = fmaf(v.w, w1, H1[3]);
            H2[0] = fmaf(v.x, w2, H2[0]); H2[1] = fmaf(v.y, w2, H2[1]);
            H2[2] = fmaf(v.z, w2, H2[2]); H2[3] = fmaf(v.w, w2, H2[3]);
        }

        float* hrow = g_h + (long long)r0 * D;
        #pragma unroll
        for (int j = 0; j < 4; j++) {
            hrow[j * D + c0] = H0[j];
            hrow[j * D + c1] = H1[j];
            hrow[j * D + c2] = H2[j];
            s0 += H0[j]; s1 += H1[j]; s2 += H2[j];
            q0 += H0[j] * H0[j]; q1 += H1[j] * H1[j]; q2 += H2[j] * H2[j];
        }
        __syncwarp();
    }

    atomicAdd(&g_sum[c0], s0);   atomicAdd(&g_sum[c1], s1);   atomicAdd(&g_sum[c2], s2);
    atomicAdd(&g_sumsq[c0], q0); atomicAdd(&g_sumsq[c1], q1); atomicAdd(&g_sumsq[c2], q2);
}

// ---------------------------------------------------------------------------
// Kernel 6: fused BN finalize + apply + relu (unchanged)
// ---------------------------------------------------------------------------
__global__ void bn_apply_kernel(const float* __restrict__ gamma,
                                const float* __restrict__ beta,
                                float* __restrict__ out, int N, int ND4) {
    __shared__ float sc[D], sh[D];
    int t = threadIdx.x;
    if (t < D) {
        float invN = 1.0f / (float)N;
        float mean = g_sum[t] * invN;
        float var = fmaxf(g_sumsq[t] * invN - mean * mean, 0.0f);
        float s = gamma[t] * rsqrtf(var + 1e-5f);
        sc[t] = s;
        sh[t] = beta[t] - mean * s;
    }
    __syncthreads();
    for (int i = blockIdx.x * blockDim.x + t; i < ND4; i += gridDim.x * blockDim.x) {
        float4 h = reinterpret_cast<const float4*>(g_h)[i];
        int cb = (i * 4) % D;
        float4 o;
        o.x = fmaxf(fmaf(h.x, sc[cb + 0], sh[cb + 0]), 0.0f);
        o.y = fmaxf(fmaf(h.y, sc[cb + 1], sh[cb + 1]), 0.0f);
        o.z = fmaxf(fmaf(h.z, sc[cb + 2], sh[cb + 2]), 0.0f);
        o.w = fmaxf(fmaf(h.w, sc[cb + 3], sh[cb + 3]), 0.0f);
        reinterpret_cast<float4*>(out)[i] = o;
    }
}

// ---------------------------------------------------------------------------
extern "C" void kernel_launch(void* const* d_in, const int* in_sizes, int n_in,
                              void* d_out, int out_size) {
    const float* feature = (const float*)d_in[0];
    const int*   src     = (const int*)d_in[1];
    const int*   dst     = (const int*)d_in[2];
    const float* W1      = (const float*)d_in[3];
    const float* b1      = (const float*)d_in[4];
    const float* W2      = (const float*)d_in[5];
    const float* b2      = (const float*)d_in[6];
    const float* gamma   = (const float*)d_in[7];
    const float* beta    = (const float*)d_in[8];
    const float* eps     = (const float*)d_in[9];
    float* out = (float*)d_out;

    int ND = in_sizes[0];
    int E  = in_sizes[1];
    int N  = ND / D;
    int ND4 = ND / 4;

    // 0. zero counts + BN accumulators
    zero_kernel<<<(N + 255) / 256, 256>>>(N);
    // 1. count in-degree
    count_kernel<<<(E + 255) / 256, 256>>>(dst, E);
    // 2. exclusive scan -> offsets + cursors (single block)
    scan_kernel<<<1, 1024>>>(N);
    // 3. fill per-dst edge lists
    fill_kernel<<<(E + 255) / 256, 256>>>(src, dst, E);
    // 4. atomic-free gather pooling (also folds (1+eps)*feature)
    gather_kernel<<<296, 256>>>(feature, eps, N);
    // 5. fused MLP + BN partial sums
    {
        static bool attr_set = false;
        size_t smem = (size_t)(18624 + MLP_WARPS * D * 4) * sizeof(float); // 86784 B
        if (!attr_set) {
            cudaFuncSetAttribute(mlp_kernel,
                                 cudaFuncAttributeMaxDynamicSharedMemorySize,
                                 (int)smem);
            attr_set = true;
        }
        mlp_kernel<<<MLP_BLOCKS, MLP_WARPS * 32, smem>>>(W1, b1, W2, b2, N);
    }
    // 6. BN finalize + apply + relu
    bn_apply_kernel<<<592, 256>>>(gamma, beta, out, N, ND4);
}